// round 1
// baseline (speedup 1.0000x reference)
#include <cuda_runtime.h>
#include <cuda_bf16.h>
#include <math.h>

// ---------------- model dims ----------------
#define BATCH      2
#define SEQ        1024
#define M_ROWS     (BATCH*SEQ)        // 2048
#define D_MODEL    768
#define D_INNER    1536
#define D_STATE    16
#define DT_RANK    48
#define D_CONV     4
#define XDBL_COLS  (DT_RANK + 2*D_STATE)   // 80
#define VOCAB      32000
#define N_LAYER    2
#define EPS        1e-5f

// ---------------- scratch (static device memory; no allocs) ----------------
__device__ float g_x    [M_ROWS * D_MODEL];
__device__ float g_xn   [M_ROWS * D_MODEL];
__device__ float g_xr   [M_ROWS * 2 * D_INNER];
__device__ float g_u    [M_ROWS * D_INNER];
__device__ float g_xdbl [M_ROWS * XDBL_COLS];
__device__ float g_delta[M_ROWS * D_INNER];
__device__ float g_y    [M_ROWS * D_INNER];

// ---------------- embedding gather ----------------
__global__ void embed_kernel(const int* __restrict__ ids,
                             const float* __restrict__ emb,
                             float* __restrict__ x)
{
    int row = blockIdx.x;
    int tok = ids[row];
    const float4* src = (const float4*)(emb + (long)tok * D_MODEL);
    float4* dst = (float4*)(x + (long)row * D_MODEL);
    for (int i = threadIdx.x; i < D_MODEL/4; i += blockDim.x)
        dst[i] = src[i];
}

// ---------------- rmsnorm: one block per row ----------------
__global__ void rmsnorm_kernel(const float* __restrict__ x,
                               const float* __restrict__ w,
                               float* __restrict__ out)
{
    __shared__ float red[8];
    int row = blockIdx.x;
    const float* xp = x + (long)row * D_MODEL;
    float s = 0.f;
    for (int i = threadIdx.x; i < D_MODEL; i += 256) {
        float v = xp[i];
        s += v * v;
    }
    #pragma unroll
    for (int o = 16; o; o >>= 1) s += __shfl_xor_sync(0xffffffffu, s, o);
    if ((threadIdx.x & 31) == 0) red[threadIdx.x >> 5] = s;
    __syncthreads();
    if (threadIdx.x < 8) {
        float t = red[threadIdx.x];
        #pragma unroll
        for (int o = 4; o; o >>= 1) t += __shfl_xor_sync(0xffu, t, o);
        if (threadIdx.x == 0) red[0] = t;
    }
    __syncthreads();
    float scale = rsqrtf(red[0] / (float)D_MODEL + EPS);
    for (int i = threadIdx.x; i < D_MODEL; i += 256)
        out[(long)row * D_MODEL + i] = xp[i] * scale * w[i];
}

// ---------------- generic SGEMM: C[M,N] = A[M,K] @ W[N,K]^T (+epilogue) ----
// mode 0: plain.  mode 1: softplus(acc + bias[n]).  mode 2: acc + ext[m*ldc+n].
// BM=BN=128, BK=8, 256 threads, 8x8 per thread. Requires M%128==0, K%8==0,
// lda/ldb row bases 16B-aligned (true for all call sites here).
__global__ __launch_bounds__(256) void sgemm_kernel(
    const float* __restrict__ A, int lda,
    const float* __restrict__ W,
    const float* __restrict__ ext,
    float* __restrict__ C, int ldc,
    int M, int N, int K, int mode)
{
    __shared__ float As[8][128];
    __shared__ float Bs[8][128];
    const int tid  = threadIdx.x;
    const int bm   = blockIdx.y * 128;
    const int bn   = blockIdx.x * 128;
    const int lrow = tid >> 1;
    const int lcol = (tid & 1) << 2;
    const int tx   = tid & 15;
    const int ty   = tid >> 4;

    float acc[8][8];
    #pragma unroll
    for (int i = 0; i < 8; i++)
        #pragma unroll
        for (int j = 0; j < 8; j++) acc[i][j] = 0.f;

    const float* Aptr  = A + (long)(bm + lrow) * lda + lcol;
    const float* Wptr  = W + (long)(bn + lrow) * K + lcol;
    const bool wvalid  = (bn + lrow) < N;

    for (int k0 = 0; k0 < K; k0 += 8) {
        float4 av = *(const float4*)(Aptr + k0);
        float4 bv = wvalid ? *(const float4*)(Wptr + k0)
                           : make_float4(0.f, 0.f, 0.f, 0.f);
        As[lcol+0][lrow] = av.x;
        As[lcol+1][lrow] = av.y;
        As[lcol+2][lrow] = av.z;
        As[lcol+3][lrow] = av.w;
        Bs[lcol+0][lrow] = bv.x;
        Bs[lcol+1][lrow] = bv.y;
        Bs[lcol+2][lrow] = bv.z;
        Bs[lcol+3][lrow] = bv.w;
        __syncthreads();
        #pragma unroll
        for (int kk = 0; kk < 8; kk++) {
            float a[8], b[8];
            *(float4*)(a)   = *(const float4*)(&As[kk][ty*8]);
            *(float4*)(a+4) = *(const float4*)(&As[kk][ty*8+4]);
            *(float4*)(b)   = *(const float4*)(&Bs[kk][tx*8]);
            *(float4*)(b+4) = *(const float4*)(&Bs[kk][tx*8+4]);
            #pragma unroll
            for (int i = 0; i < 8; i++)
                #pragma unroll
                for (int j = 0; j < 8; j++)
                    acc[i][j] = fmaf(a[i], b[j], acc[i][j]);
        }
        __syncthreads();
    }

    #pragma unroll
    for (int i = 0; i < 8; i++) {
        int row = bm + ty*8 + i;
        #pragma unroll
        for (int j = 0; j < 8; j++) {
            int col = bn + tx*8 + j;
            if (col < N) {
                float v = acc[i][j];
                if (mode == 1) {
                    v += ext[col];
                    v = (v > 20.f) ? v : log1pf(__expf(v));
                } else if (mode == 2) {
                    v += ext[(long)row * ldc + col];
                }
                C[(long)row * ldc + col] = v;
            }
        }
    }
}

// ---------------- causal depthwise conv(4) + bias + silu ----------------
// input u_in = xr[:, :D_INNER] (row stride 2*D_INNER); output u (row stride D_INNER)
__global__ void conv_silu_kernel(const float* __restrict__ xr,
                                 const float* __restrict__ cw,
                                 const float* __restrict__ cb,
                                 float* __restrict__ u)
{
    int idx = blockIdx.x * blockDim.x + threadIdx.x;
    if (idx >= M_ROWS * D_INNER) return;
    int c = idx % D_INNER;
    int m = idx / D_INNER;
    int l = m % SEQ;
    float w0 = cw[c*4+0], w1 = cw[c*4+1], w2 = cw[c*4+2], w3 = cw[c*4+3];
    const float* base = xr + (long)m * (2*D_INNER) + c;
    float acc = cb[c] + w3 * base[0];
    if (l >= 1) acc += w2 * base[-(2*D_INNER)];
    if (l >= 2) acc += w1 * base[-2*(2*D_INNER)];
    if (l >= 3) acc += w0 * base[-3*(2*D_INNER)];
    u[idx] = acc / (1.f + __expf(-acc));
}

// ---------------- selective scan (fused with u*D and silu(res) gating) ----
// one 16-lane group per (batch, channel); lane = state index n
__global__ void scan_kernel(const float* __restrict__ delta,
                            const float* __restrict__ u,
                            const float* __restrict__ xdbl,
                            const float* __restrict__ xr,
                            const float* __restrict__ A_log,
                            const float* __restrict__ Dp,
                            float* __restrict__ y)
{
    int gid  = blockIdx.x * (blockDim.x / 16) + (threadIdx.x / 16);
    int lane = threadIdx.x & 15;
    if (gid >= BATCH * D_INNER) return;
    int b  = gid / D_INNER;
    int di = gid % D_INNER;

    float An = -__expf(A_log[di * D_STATE + lane]);
    float Dv = Dp[di];
    float h  = 0.f;

    long m0 = (long)b * SEQ;
    const float* dptr = delta + m0 * D_INNER + di;
    const float* uptr = u     + m0 * D_INNER + di;
    const float* rptr = xr    + m0 * (2*D_INNER) + D_INNER + di;
    const float* bptr = xdbl  + m0 * XDBL_COLS + DT_RANK + lane;
    const float* cptr = xdbl  + m0 * XDBL_COLS + DT_RANK + D_STATE + lane;
    float* yptr       = y     + m0 * D_INNER + di;

    for (int l = 0; l < SEQ; l++) {
        float dv = dptr[(long)l * D_INNER];
        float uv = uptr[(long)l * D_INNER];
        float Bv = bptr[(long)l * XDBL_COLS];
        float Cv = cptr[(long)l * XDBL_COLS];
        float dA = __expf(dv * An);
        h = fmaf(dA, h, dv * Bv * uv);
        float p = h * Cv;
        p += __shfl_xor_sync(0xffffffffu, p, 8);
        p += __shfl_xor_sync(0xffffffffu, p, 4);
        p += __shfl_xor_sync(0xffffffffu, p, 2);
        p += __shfl_xor_sync(0xffffffffu, p, 1);
        if (lane == 0) {
            float rv = rptr[(long)l * (2*D_INNER)];
            float yv = p + uv * Dv;
            yptr[(long)l * D_INNER] = yv * (rv / (1.f + __expf(-rv)));
        }
    }
}

// ---------------- launch ----------------
extern "C" void kernel_launch(void* const* d_in, const int* in_sizes, int n_in,
                              void* d_out, int out_size)
{
    const int*   ids    = (const int*)  d_in[0];
    const float* emb    = (const float*)d_in[1];
    const float* normw  = (const float*)d_in[2];
    const float* inpw   = (const float*)d_in[3];
    const float* convw  = (const float*)d_in[4];
    const float* convb  = (const float*)d_in[5];
    const float* xprojw = (const float*)d_in[6];
    const float* dtpw   = (const float*)d_in[7];
    const float* dtpb   = (const float*)d_in[8];
    const float* Alog   = (const float*)d_in[9];
    const float* Dw     = (const float*)d_in[10];
    const float* outpw  = (const float*)d_in[11];
    const float* normf  = (const float*)d_in[12];
    float* out = (float*)d_out;

    float *x, *xn, *xr, *u, *xdbl, *delta, *y;
    cudaGetSymbolAddress((void**)&x,     g_x);
    cudaGetSymbolAddress((void**)&xn,    g_xn);
    cudaGetSymbolAddress((void**)&xr,    g_xr);
    cudaGetSymbolAddress((void**)&u,     g_u);
    cudaGetSymbolAddress((void**)&xdbl,  g_xdbl);
    cudaGetSymbolAddress((void**)&delta, g_delta);
    cudaGetSymbolAddress((void**)&y,     g_y);

    embed_kernel<<<M_ROWS, 256>>>(ids, emb, x);

    for (int lyr = 0; lyr < N_LAYER; lyr++) {
        rmsnorm_kernel<<<M_ROWS, 256>>>(x, normw + lyr * D_MODEL, xn);

        // in_proj: (2048,768) @ (3072,768)^T -> xr (2048,3072)
        sgemm_kernel<<<dim3(2*2*D_INNER/128, M_ROWS/128), 256>>>(
            xn, D_MODEL, inpw + (long)lyr * 2*D_INNER*D_MODEL, nullptr,
            xr, 2*D_INNER, M_ROWS, 2*D_INNER, D_MODEL, 0);

        // depthwise conv + silu -> u
        conv_silu_kernel<<<(M_ROWS*D_INNER + 255)/256, 256>>>(
            xr, convw + lyr * D_INNER*D_CONV, convb + lyr * D_INNER, u);

        // x_proj: (2048,1536) @ (80,1536)^T -> xdbl (2048,80)
        sgemm_kernel<<<dim3(1, M_ROWS/128), 256>>>(
            u, D_INNER, xprojw + (long)lyr * XDBL_COLS*D_INNER, nullptr,
            xdbl, XDBL_COLS, M_ROWS, XDBL_COLS, D_INNER, 0);

        // dt_proj + bias + softplus: (2048,48) @ (1536,48)^T -> delta (2048,1536)
        sgemm_kernel<<<dim3(D_INNER/128, M_ROWS/128), 256>>>(
            xdbl, XDBL_COLS, dtpw + (long)lyr * D_INNER*DT_RANK,
            dtpb + lyr * D_INNER,
            delta, D_INNER, M_ROWS, D_INNER, DT_RANK, 1);

        // selective scan + D skip + silu(res) gate -> y
        scan_kernel<<<(BATCH*D_INNER)/16, 256>>>(
            delta, u, xdbl, xr, Alog + (long)lyr * D_INNER*D_STATE,
            Dw + lyr * D_INNER, y);

        // out_proj + residual: (2048,1536) @ (768,1536)^T + x -> x
        sgemm_kernel<<<dim3(D_MODEL/128, M_ROWS/128), 256>>>(
            y, D_INNER, outpw + (long)lyr * D_MODEL*D_INNER, x,
            x, D_MODEL, M_ROWS, D_MODEL, D_INNER, 2);
    }

    rmsnorm_kernel<<<M_ROWS, 256>>>(x, normf, xn);

    // logits: (2048,768) @ (32000,768)^T -> out (2048,32000)
    sgemm_kernel<<<dim3(VOCAB/128, M_ROWS/128), 256>>>(
        xn, D_MODEL, emb, nullptr, out, VOCAB, M_ROWS, VOCAB, D_MODEL, 0);
}

// round 3
// speedup vs baseline: 2.0548x; 2.0548x over previous
#include <cuda_runtime.h>
#include <cuda_bf16.h>
#include <math.h>
#include <stdint.h>

// ---------------- model dims ----------------
#define BATCH      2
#define SEQ        1024
#define M_ROWS     (BATCH*SEQ)        // 2048
#define D_MODEL    768
#define D_INNER    1536
#define D_STATE    16
#define DT_RANK    48
#define D_CONV     4
#define XDBL_COLS  (DT_RANK + 2*D_STATE)   // 80
#define VOCAB      32000
#define N_LAYER    2
#define EPS        1e-5f

// ---------------- fp32 scratch ----------------
__device__ __align__(16) float g_x    [M_ROWS * D_MODEL];
__device__ __align__(16) float g_xn   [M_ROWS * D_MODEL];
__device__ __align__(16) float g_xr   [M_ROWS * 2 * D_INNER];
__device__ __align__(16) float g_u    [M_ROWS * D_INNER];
__device__ __align__(16) float g_xdbl [M_ROWS * XDBL_COLS];
__device__ __align__(16) float g_delta[M_ROWS * D_INNER];
__device__ __align__(16) float g_y    [M_ROWS * D_INNER];

// ---------------- bf16 hi/lo split buffers ----------------
__device__ __align__(16) __nv_bfloat16 g_emb_h [VOCAB*D_MODEL];
__device__ __align__(16) __nv_bfloat16 g_emb_l [VOCAB*D_MODEL];
__device__ __align__(16) __nv_bfloat16 g_inpw_h[N_LAYER*2*D_INNER*D_MODEL];
__device__ __align__(16) __nv_bfloat16 g_inpw_l[N_LAYER*2*D_INNER*D_MODEL];
__device__ __align__(16) __nv_bfloat16 g_outpw_h[N_LAYER*D_MODEL*D_INNER];
__device__ __align__(16) __nv_bfloat16 g_outpw_l[N_LAYER*D_MODEL*D_INNER];
__device__ __align__(16) __nv_bfloat16 g_xn_h[M_ROWS*D_MODEL];
__device__ __align__(16) __nv_bfloat16 g_xn_l[M_ROWS*D_MODEL];
__device__ __align__(16) __nv_bfloat16 g_u_h [M_ROWS*D_INNER];
__device__ __align__(16) __nv_bfloat16 g_u_l [M_ROWS*D_INNER];
__device__ __align__(16) __nv_bfloat16 g_y_h [M_ROWS*D_INNER];
__device__ __align__(16) __nv_bfloat16 g_y_l [M_ROWS*D_INNER];
__device__ __align__(16) __nv_bfloat16 g_xpw_h[128*D_INNER];      // x_proj W padded 80->128 rows
__device__ __align__(16) __nv_bfloat16 g_xpw_l[128*D_INNER];
__device__ __align__(16) __nv_bfloat16 g_dtw_h[D_INNER*64];       // dt_proj W padded K 48->64
__device__ __align__(16) __nv_bfloat16 g_dtw_l[D_INNER*64];
__device__ __align__(16) __nv_bfloat16 g_xdp_h[M_ROWS*64];        // delta-input padded K 48->64
__device__ __align__(16) __nv_bfloat16 g_xdp_l[M_ROWS*64];

// ================= small kernels =================
__global__ void embed_kernel(const int* __restrict__ ids,
                             const float* __restrict__ emb,
                             float* __restrict__ x)
{
    int row = blockIdx.x;
    int tok = ids[row];
    const float4* src = (const float4*)(emb + (long)tok * D_MODEL);
    float4* dst = (float4*)(x + (long)row * D_MODEL);
    for (int i = threadIdx.x; i < D_MODEL/4; i += blockDim.x) dst[i] = src[i];
}

__global__ void rmsnorm_kernel(const float* __restrict__ x,
                               const float* __restrict__ w,
                               float* __restrict__ out)
{
    __shared__ float red[8];
    int row = blockIdx.x;
    const float* xp = x + (long)row * D_MODEL;
    float s = 0.f;
    for (int i = threadIdx.x; i < D_MODEL; i += 256) { float v = xp[i]; s += v*v; }
    #pragma unroll
    for (int o = 16; o; o >>= 1) s += __shfl_xor_sync(0xffffffffu, s, o);
    if ((threadIdx.x & 31) == 0) red[threadIdx.x >> 5] = s;
    __syncthreads();
    if (threadIdx.x < 8) {
        float t = red[threadIdx.x];
        #pragma unroll
        for (int o = 4; o; o >>= 1) t += __shfl_xor_sync(0xffu, t, o);
        if (threadIdx.x == 0) red[0] = t;
    }
    __syncthreads();
    float scale = rsqrtf(red[0] / (float)D_MODEL + EPS);
    for (int i = threadIdx.x; i < D_MODEL; i += 256)
        out[(long)row * D_MODEL + i] = xp[i] * scale * w[i];
}

// fp32 -> bf16 hi/lo split
__global__ void split_kernel(const float* __restrict__ s, int n,
                             __nv_bfloat16* __restrict__ h, __nv_bfloat16* __restrict__ l)
{
    int i = blockIdx.x * blockDim.x + threadIdx.x;
    if (i < n) {
        float v = s[i];
        __nv_bfloat16 hb = __float2bfloat16(v);
        h[i] = hb;
        l[i] = __float2bfloat16(v - __bfloat162float(hb));
    }
}

__global__ void split_pad_rows(const float* __restrict__ s, int rows_real, int K,
                               int rows_pad,
                               __nv_bfloat16* __restrict__ h, __nv_bfloat16* __restrict__ l)
{
    int i = blockIdx.x * blockDim.x + threadIdx.x;
    int n = rows_pad * K;
    if (i >= n) return;
    int r = i / K, k = i % K;
    float v = (r < rows_real) ? s[(long)r * K + k] : 0.f;
    __nv_bfloat16 hb = __float2bfloat16(v);
    h[i] = hb;
    l[i] = __float2bfloat16(v - __bfloat162float(hb));
}

__global__ void split_pad_cols(const float* __restrict__ s, int rows, int src_ld,
                               int k_take, int k_pad,
                               __nv_bfloat16* __restrict__ h, __nv_bfloat16* __restrict__ l)
{
    int i = blockIdx.x * blockDim.x + threadIdx.x;
    int n = rows * k_pad;
    if (i >= n) return;
    int r = i / k_pad, k = i % k_pad;
    float v = (k < k_take) ? s[(long)r * src_ld + k] : 0.f;
    __nv_bfloat16 hb = __float2bfloat16(v);
    h[i] = hb;
    l[i] = __float2bfloat16(v - __bfloat162float(hb));
}

__global__ void conv_silu_kernel(const float* __restrict__ xr,
                                 const float* __restrict__ cw,
                                 const float* __restrict__ cb,
                                 float* __restrict__ u)
{
    int idx = blockIdx.x * blockDim.x + threadIdx.x;
    if (idx >= M_ROWS * D_INNER) return;
    int c = idx % D_INNER;
    int m = idx / D_INNER;
    int l = m % SEQ;
    float w0 = cw[c*4+0], w1 = cw[c*4+1], w2 = cw[c*4+2], w3 = cw[c*4+3];
    const float* base = xr + (long)m * (2*D_INNER) + c;
    float acc = cb[c] + w3 * base[0];
    if (l >= 1) acc += w2 * base[-(2*D_INNER)];
    if (l >= 2) acc += w1 * base[-2*(2*D_INNER)];
    if (l >= 3) acc += w0 * base[-3*(2*D_INNER)];
    u[idx] = acc / (1.f + __expf(-acc));
}

__global__ void scan_kernel(const float* __restrict__ delta,
                            const float* __restrict__ u,
                            const float* __restrict__ xdbl,
                            const float* __restrict__ xr,
                            const float* __restrict__ A_log,
                            const float* __restrict__ Dp,
                            float* __restrict__ y)
{
    int gid  = blockIdx.x * (blockDim.x / 16) + (threadIdx.x / 16);
    int lane = threadIdx.x & 15;
    if (gid >= BATCH * D_INNER) return;
    int b  = gid / D_INNER;
    int di = gid % D_INNER;

    float An = -__expf(A_log[di * D_STATE + lane]);
    float Dv = Dp[di];
    float h  = 0.f;

    long m0 = (long)b * SEQ;
    const float* dptr = delta + m0 * D_INNER + di;
    const float* uptr = u     + m0 * D_INNER + di;
    const float* rptr = xr    + m0 * (2*D_INNER) + D_INNER + di;
    const float* bptr = xdbl  + m0 * XDBL_COLS + DT_RANK + lane;
    const float* cptr = xdbl  + m0 * XDBL_COLS + DT_RANK + D_STATE + lane;
    float* yptr       = y     + m0 * D_INNER + di;

    for (int l = 0; l < SEQ; l++) {
        float dv = dptr[(long)l * D_INNER];
        float uv = uptr[(long)l * D_INNER];
        float Bv = bptr[(long)l * XDBL_COLS];
        float Cv = cptr[(long)l * XDBL_COLS];
        float dA = __expf(dv * An);
        h = fmaf(dA, h, dv * Bv * uv);
        float p = h * Cv;
        p += __shfl_xor_sync(0xffffffffu, p, 8);
        p += __shfl_xor_sync(0xffffffffu, p, 4);
        p += __shfl_xor_sync(0xffffffffu, p, 2);
        p += __shfl_xor_sync(0xffffffffu, p, 1);
        if (lane == 0) {
            float rv = rptr[(long)l * (2*D_INNER)];
            float yv = p + uv * Dv;
            yptr[(long)l * D_INNER] = yv * (rv / (1.f + __expf(-rv)));
        }
    }
}

// ================= mma.sync split-bf16 GEMM =================
// C[M,N] = (Ah+Al)[M,K] @ (Bh+Bl)[N,K]^T, fp32 accum, 3-term split (drop lo*lo).
// 128x128x32 tiles, 8 warps (2Mx4N), warp tile 64x32, cp.async double buffer.
// mode 0: plain   mode 1: softplus(acc + ext[col])   mode 2: acc + ext[row*ldc+col]
// Requires: M%128==0, K%32==0 and K>=64, B buffers padded to 128-row multiples.
#define GPITCH 40                      // bf16 elems per smem row (80B, conflict-free)
#define GTILE  (128*GPITCH)            // elems per tile array
#define GSMEM_BYTES (2*4*GTILE*2)      // 2 stages x 4 arrays  = 81920 B

__device__ __forceinline__ uint32_t smem_u32(const void* p) {
    uint32_t a;
    asm("{ .reg .u64 t; cvta.to.shared.u64 t, %1; cvt.u32.u64 %0, t; }" : "=r"(a) : "l"(p));
    return a;
}

#define LDSM_X4(r, addr) \
    asm volatile("ldmatrix.sync.aligned.m8n8.x4.shared.b16 {%0,%1,%2,%3}, [%4];" \
        : "=r"((r)[0]),"=r"((r)[1]),"=r"((r)[2]),"=r"((r)[3]) : "r"(addr))

#define MMA_BF16(c, a, b) \
    asm volatile("mma.sync.aligned.m16n8k16.row.col.f32.bf16.bf16.f32 " \
        "{%0,%1,%2,%3},{%4,%5,%6,%7},{%8,%9},{%0,%1,%2,%3};" \
        : "+f"((c)[0]),"+f"((c)[1]),"+f"((c)[2]),"+f"((c)[3]) \
        : "r"((a)[0]),"r"((a)[1]),"r"((a)[2]),"r"((a)[3]),"r"((b)[0]),"r"((b)[1]))

__global__ void __launch_bounds__(256, 2) mma_gemm(
    const __nv_bfloat16* __restrict__ Ah, const __nv_bfloat16* __restrict__ Al,
    const __nv_bfloat16* __restrict__ Bh, const __nv_bfloat16* __restrict__ Bl,
    int K, float* __restrict__ C, int ldc, int Nreal,
    const float* __restrict__ ext, int mode)
{
    extern __shared__ __nv_bfloat16 sm[];
    const uint32_t sbase = smem_u32(sm);
    const int tid  = threadIdx.x;
    const int lane = tid & 31;
    const int w    = tid >> 5;
    const int wm   = (w >> 2) << 6;     // 0 or 64
    const int wn   = (w & 3) << 5;      // 0,32,64,96
    const long bm  = (long)blockIdx.y * 128;
    const long bn  = (long)blockIdx.x * 128;

    float acc[4][4][4];
    #pragma unroll
    for (int i = 0; i < 4; i++)
        #pragma unroll
        for (int j = 0; j < 4; j++)
            #pragma unroll
            for (int e = 0; e < 4; e++) acc[i][j][e] = 0.f;

    const __nv_bfloat16* bases[4] = {Ah, Al, Bh, Bl};

    // ---- async stage loader: 4 arrays x 128 rows x 32 bf16 ----
    #define LOAD_STAGE(s, kc) do {                                            \
        int _k0 = (kc) << 5;                                                  \
        _Pragma("unroll")                                                     \
        for (int _it = 0; _it < 8; _it++) {                                   \
            int _i   = _it * 256 + tid;                                       \
            int _arr = _i >> 9;                                               \
            int _idx = _i & 511;                                              \
            int _row = _idx >> 2;                                             \
            int _ch  = _idx & 3;                                              \
            const __nv_bfloat16* _g = bases[_arr]                             \
                + ((_arr < 2 ? bm : bn) + _row) * (long)K + _k0 + _ch * 8;    \
            uint32_t _d = sbase + (((s)*4 + _arr) * GTILE                     \
                          + _row * GPITCH + _ch * 8) * 2;                     \
            asm volatile("cp.async.cg.shared.global [%0], [%1], 16;"          \
                         :: "r"(_d), "l"(_g));                                \
        }                                                                     \
        asm volatile("cp.async.commit_group;" ::: "memory");                  \
    } while (0)

    const int NC = K >> 5;              // 32-wide chunks, NC >= 2 guaranteed
    LOAD_STAGE(0, 0);
    LOAD_STAGE(1, 1);

    for (int c = 0; c < NC; c++) {
        if (c + 1 < NC) asm volatile("cp.async.wait_group 1;" ::: "memory");
        else            asm volatile("cp.async.wait_group 0;" ::: "memory");
        __syncthreads();

        const int s = c & 1;
        const uint32_t aH = sbase + ((s*4 + 0) * GTILE) * 2;
        const uint32_t aL = sbase + ((s*4 + 1) * GTILE) * 2;
        const __nv_bfloat16* bH = sm + (s*4 + 2) * GTILE;
        const __nv_bfloat16* bL = sm + (s*4 + 3) * GTILE;

        #pragma unroll
        for (int ks = 0; ks < 2; ks++) {
            const int k0 = ks << 4;
            // A fragments via ldmatrix.x4 (row-major A, canonical layout)
            const uint32_t aoff = ((wm + (lane & 15)) * GPITCH
                                   + k0 + ((lane >> 4) << 3)) * 2;
            uint32_t ah[4][4], al[4][4];
            #pragma unroll
            for (int mi = 0; mi < 4; mi++) {
                LDSM_X4(ah[mi], aH + aoff + mi * 16 * GPITCH * 2);
                LDSM_X4(al[mi], aL + aoff + mi * 16 * GPITCH * 2);
            }
            // B fragments via direct paired LDS (W[n][k] row-major)
            const int nrow = wn + (lane >> 2);
            const int kk   = k0 + ((lane & 3) << 1);
            uint32_t bh[4][2], bl[4][2];
            #pragma unroll
            for (int ni = 0; ni < 4; ni++) {
                int o = (nrow + ni * 8) * GPITCH + kk;
                bh[ni][0] = *(const uint32_t*)(bH + o);
                bh[ni][1] = *(const uint32_t*)(bH + o + 8);
                bl[ni][0] = *(const uint32_t*)(bL + o);
                bl[ni][1] = *(const uint32_t*)(bL + o + 8);
            }
            #pragma unroll
            for (int mi = 0; mi < 4; mi++)
                #pragma unroll
                for (int ni = 0; ni < 4; ni++)
                    MMA_BF16(acc[mi][ni], ah[mi], bh[ni]);
            #pragma unroll
            for (int mi = 0; mi < 4; mi++)
                #pragma unroll
                for (int ni = 0; ni < 4; ni++)
                    MMA_BF16(acc[mi][ni], ah[mi], bl[ni]);
            #pragma unroll
            for (int mi = 0; mi < 4; mi++)
                #pragma unroll
                for (int ni = 0; ni < 4; ni++)
                    MMA_BF16(acc[mi][ni], al[mi], bh[ni]);
        }
        __syncthreads();
        if (c + 2 < NC) LOAD_STAGE(s, c + 2);
    }

    // ---- epilogue ----
    const int g  = lane >> 2;
    const int cc = (lane & 3) << 1;
    #pragma unroll
    for (int mi = 0; mi < 4; mi++) {
        #pragma unroll
        for (int ni = 0; ni < 4; ni++) {
            int col = (int)bn + wn + ni * 8 + cc;
            if (col >= Nreal) continue;
            long row0 = bm + wm + mi * 16 + g;
            float v0 = acc[mi][ni][0], v1 = acc[mi][ni][1];
            float v2 = acc[mi][ni][2], v3 = acc[mi][ni][3];
            if (mode == 1) {
                float b0 = ext[col], b1 = ext[col + 1];
                v0 += b0; v1 += b1; v2 += b0; v3 += b1;
                v0 = (v0 > 20.f) ? v0 : log1pf(__expf(v0));
                v1 = (v1 > 20.f) ? v1 : log1pf(__expf(v1));
                v2 = (v2 > 20.f) ? v2 : log1pf(__expf(v2));
                v3 = (v3 > 20.f) ? v3 : log1pf(__expf(v3));
            } else if (mode == 2) {
                v0 += ext[row0 * ldc + col];
                v1 += ext[row0 * ldc + col + 1];
                v2 += ext[(row0 + 8) * ldc + col];
                v3 += ext[(row0 + 8) * ldc + col + 1];
            }
            *(float2*)(C + row0 * ldc + col)       = make_float2(v0, v1);
            *(float2*)(C + (row0 + 8) * ldc + col) = make_float2(v2, v3);
        }
    }
}

// ================= launch =================
extern "C" void kernel_launch(void* const* d_in, const int* in_sizes, int n_in,
                              void* d_out, int out_size)
{
    const int*   ids    = (const int*)  d_in[0];
    const float* emb    = (const float*)d_in[1];
    const float* normw  = (const float*)d_in[2];
    const float* inpw   = (const float*)d_in[3];
    const float* convw  = (const float*)d_in[4];
    const float* convb  = (const float*)d_in[5];
    const float* xprojw = (const float*)d_in[6];
    const float* dtpw   = (const float*)d_in[7];
    const float* dtpb   = (const float*)d_in[8];
    const float* Alog   = (const float*)d_in[9];
    const float* Dw     = (const float*)d_in[10];
    const float* outpw  = (const float*)d_in[11];
    const float* normf  = (const float*)d_in[12];
    float* out = (float*)d_out;

    float *x, *xn, *xr, *u, *xdbl, *delta, *y;
    cudaGetSymbolAddress((void**)&x,     g_x);
    cudaGetSymbolAddress((void**)&xn,    g_xn);
    cudaGetSymbolAddress((void**)&xr,    g_xr);
    cudaGetSymbolAddress((void**)&u,     g_u);
    cudaGetSymbolAddress((void**)&xdbl,  g_xdbl);
    cudaGetSymbolAddress((void**)&delta, g_delta);
    cudaGetSymbolAddress((void**)&y,     g_y);

    __nv_bfloat16 *emb_h, *emb_l, *inpw_h, *inpw_l, *outpw_h, *outpw_l;
    __nv_bfloat16 *xn_h, *xn_l, *u_h, *u_l, *y_h, *y_l;
    __nv_bfloat16 *xpw_h, *xpw_l, *dtw_h, *dtw_l, *xdp_h, *xdp_l;
    cudaGetSymbolAddress((void**)&emb_h,  g_emb_h);   cudaGetSymbolAddress((void**)&emb_l,  g_emb_l);
    cudaGetSymbolAddress((void**)&inpw_h, g_inpw_h);  cudaGetSymbolAddress((void**)&inpw_l, g_inpw_l);
    cudaGetSymbolAddress((void**)&outpw_h,g_outpw_h); cudaGetSymbolAddress((void**)&outpw_l,g_outpw_l);
    cudaGetSymbolAddress((void**)&xn_h,   g_xn_h);    cudaGetSymbolAddress((void**)&xn_l,   g_xn_l);
    cudaGetSymbolAddress((void**)&u_h,    g_u_h);     cudaGetSymbolAddress((void**)&u_l,    g_u_l);
    cudaGetSymbolAddress((void**)&y_h,    g_y_h);     cudaGetSymbolAddress((void**)&y_l,    g_y_l);
    cudaGetSymbolAddress((void**)&xpw_h,  g_xpw_h);   cudaGetSymbolAddress((void**)&xpw_l,  g_xpw_l);
    cudaGetSymbolAddress((void**)&dtw_h,  g_dtw_h);   cudaGetSymbolAddress((void**)&dtw_l,  g_dtw_l);
    cudaGetSymbolAddress((void**)&xdp_h,  g_xdp_h);   cudaGetSymbolAddress((void**)&xdp_l,  g_xdp_l);

    cudaFuncSetAttribute(mma_gemm, cudaFuncAttributeMaxDynamicSharedMemorySize,
                         GSMEM_BYTES);

    #define SPLIT(src, n, h, l) \
        split_kernel<<<((n) + 511) / 512, 512>>>(src, n, h, l)

    // weight conversions (deterministic, every call)
    SPLIT(emb,   VOCAB * D_MODEL,                 emb_h,   emb_l);
    SPLIT(inpw,  N_LAYER * 2 * D_INNER * D_MODEL, inpw_h,  inpw_l);
    SPLIT(outpw, N_LAYER * D_MODEL * D_INNER,     outpw_h, outpw_l);

    embed_kernel<<<M_ROWS, 256>>>(ids, emb, x);

    for (int lyr = 0; lyr < N_LAYER; lyr++) {
        rmsnorm_kernel<<<M_ROWS, 256>>>(x, normw + lyr * D_MODEL, xn);
        SPLIT(xn, M_ROWS * D_MODEL, xn_h, xn_l);

        // in_proj: (2048,768) @ (3072,768)^T -> xr
        mma_gemm<<<dim3(2*D_INNER/128, M_ROWS/128), 256, GSMEM_BYTES>>>(
            xn_h, xn_l,
            inpw_h + (long)lyr * 2*D_INNER*D_MODEL,
            inpw_l + (long)lyr * 2*D_INNER*D_MODEL,
            D_MODEL, xr, 2*D_INNER, 2*D_INNER, nullptr, 0);

        conv_silu_kernel<<<(M_ROWS*D_INNER + 255)/256, 256>>>(
            xr, convw + lyr * D_INNER*D_CONV, convb + lyr * D_INNER, u);
        SPLIT(u, M_ROWS * D_INNER, u_h, u_l);

        // x_proj: (2048,1536) @ (80,1536)^T  (W padded to 128 rows) -> xdbl
        {
            int n = 128 * D_INNER;
            split_pad_rows<<<(n + 511)/512, 512>>>(
                xprojw + (long)lyr * XDBL_COLS * D_INNER, XDBL_COLS, D_INNER, 128,
                xpw_h, xpw_l);
        }
        mma_gemm<<<dim3(1, M_ROWS/128), 256, GSMEM_BYTES>>>(
            u_h, u_l, xpw_h, xpw_l,
            D_INNER, xdbl, XDBL_COLS, XDBL_COLS, nullptr, 0);

        // dt_proj (K padded 48->64) + bias + softplus -> delta
        {
            int n1 = M_ROWS * 64;
            split_pad_cols<<<(n1 + 511)/512, 512>>>(xdbl, M_ROWS, XDBL_COLS,
                                                    DT_RANK, 64, xdp_h, xdp_l);
            int n2 = D_INNER * 64;
            split_pad_cols<<<(n2 + 511)/512, 512>>>(
                dtpw + (long)lyr * D_INNER * DT_RANK, D_INNER, DT_RANK,
                DT_RANK, 64, dtw_h, dtw_l);
        }
        mma_gemm<<<dim3(D_INNER/128, M_ROWS/128), 256, GSMEM_BYTES>>>(
            xdp_h, xdp_l, dtw_h, dtw_l,
            64, delta, D_INNER, D_INNER, dtpb + lyr * D_INNER, 1);

        // selective scan
        scan_kernel<<<(BATCH*D_INNER)/16, 256>>>(
            delta, u, xdbl, xr, Alog + (long)lyr * D_INNER*D_STATE,
            Dw + lyr * D_INNER, y);
        SPLIT(y, M_ROWS * D_INNER, y_h, y_l);

        // out_proj + residual -> x
        mma_gemm<<<dim3(D_MODEL/128, M_ROWS/128), 256, GSMEM_BYTES>>>(
            y_h, y_l,
            outpw_h + (long)lyr * D_MODEL*D_INNER,
            outpw_l + (long)lyr * D_MODEL*D_INNER,
            D_INNER, x, D_MODEL, D_MODEL, x, 2);
    }

    rmsnorm_kernel<<<M_ROWS, 256>>>(x, normf, xn);
    SPLIT(xn, M_ROWS * D_MODEL, xn_h, xn_l);

    // logits: (2048,768) @ (32000,768)^T -> out
    mma_gemm<<<dim3(VOCAB/128, M_ROWS/128), 256, GSMEM_BYTES>>>(
        xn_h, xn_l, emb_h, emb_l,
        D_MODEL, out, VOCAB, VOCAB, nullptr, 0);
}